// round 3
// baseline (speedup 1.0000x reference)
#include <cuda_runtime.h>

// S2Conv: channel-shifted signal -> cross-channel conv (window 9, per-channel w)
// -> per-channel batchnorm over (N,T) -> gamma/beta -> relu.
// N=64, C=128, T=2048, S=9, D=1.

#define Nn 64
#define Cc 128
#define Tt 2048
#define Ss 9
#define TB 256   // time tile per block
#define CG 16    // output channels per block

__device__ float g_sum[Cc];
__device__ float g_sumsq[Cc];
__device__ float g_scale[Cc];
__device__ float g_bias[Cc];

__global__ void zero_kernel() {
    int i = threadIdx.x;
    if (i < Cc) { g_sum[i] = 0.0f; g_sumsq[i] = 0.0f; }
}

// Pass 1: conv + per-channel partial stats.
// Block: one n, CG output channels, TB times. 256 threads.
// Thread: 4 channels x 4 consecutive t (float4 path through smem).
__global__ __launch_bounds__(256) void conv_stats_kernel(
    const float* __restrict__ x,
    const float* __restrict__ w,
    float* __restrict__ out)
{
    __shared__ float tile[CG + 8][TB];   // pre-shifted xs, 24 x 256 = 24KB
    __shared__ float s_w[CG][Ss];
    __shared__ float s_sum[CG], s_sq[CG];

    const int t0  = blockIdx.x * TB;
    const int cg0 = blockIdx.y * CG;
    const int n   = blockIdx.z;
    const int tid = threadIdx.x;

    if (tid < CG * Ss) {
        int cl = tid / Ss, s = tid % Ss;
        s_w[cl][s] = w[(cg0 + cl) * Ss + s];
    }
    if (tid < CG) { s_sum[tid] = 0.0f; s_sq[tid] = 0.0f; }

    // tile[lc][j] = xs[n, cg0-4+lc, t0+j]; xs[n,cc,t] = x[n,cc,t+4-cc%9] zero-padded.
    const float* xn = x + (size_t)n * Cc * Tt;
    #pragma unroll
    for (int i = tid; i < (CG + 8) * TB; i += 256) {
        int lc = i >> 8;           // / TB
        int j  = i & (TB - 1);
        int cc = cg0 - 4 + lc;
        float v = 0.0f;
        if (cc >= 0 && cc < Cc) {
            int off = 4 - (cc % 9);
            int ts  = t0 + j + off;
            if (ts >= 0 && ts < Tt) v = xn[cc * Tt + ts];
        }
        tile[lc][j] = v;
    }
    __syncthreads();

    const int g   = tid >> 6;        // channel subgroup 0..3
    const int jq  = (tid & 63) * 4;  // starting t within tile
    const int clb = g * 4;           // local channel base

    // 12 tap rows as float4 (rows clb .. clb+11)
    float4 tp[12];
    #pragma unroll
    for (int r = 0; r < 12; r++)
        tp[r] = *reinterpret_cast<const float4*>(&tile[clb + r][jq]);

    // FIX vs R2: include cg0 in the output base.
    float* outn = out + ((size_t)n * Cc + cg0) * Tt + t0 + jq;
    float lsum[4], lsq[4];

    #pragma unroll
    for (int cl = 0; cl < 4; cl++) {
        float4 a = make_float4(0.f, 0.f, 0.f, 0.f);
        #pragma unroll
        for (int s = 0; s < Ss; s++) {
            float wv = s_w[clb + cl][s];
            a.x = fmaf(wv, tp[cl + s].x, a.x);
            a.y = fmaf(wv, tp[cl + s].y, a.y);
            a.z = fmaf(wv, tp[cl + s].z, a.z);
            a.w = fmaf(wv, tp[cl + s].w, a.w);
        }
        *reinterpret_cast<float4*>(outn + (size_t)(clb + cl) * Tt) = a;
        lsum[cl] = (a.x + a.y) + (a.z + a.w);
        lsq[cl]  = fmaf(a.x, a.x, fmaf(a.y, a.y, fmaf(a.z, a.z, a.w * a.w)));
    }

    // Warp reduce (all lanes in a warp share the same channel set).
    #pragma unroll
    for (int cl = 0; cl < 4; cl++) {
        #pragma unroll
        for (int o = 16; o > 0; o >>= 1) {
            lsum[cl] += __shfl_down_sync(0xffffffffu, lsum[cl], o);
            lsq[cl]  += __shfl_down_sync(0xffffffffu, lsq[cl],  o);
        }
    }
    if ((tid & 31) == 0) {
        #pragma unroll
        for (int cl = 0; cl < 4; cl++) {
            atomicAdd(&s_sum[clb + cl], lsum[cl]);
            atomicAdd(&s_sq[clb + cl],  lsq[cl]);
        }
    }
    __syncthreads();
    if (tid < CG) {
        atomicAdd(&g_sum[cg0 + tid],   s_sum[tid]);
        atomicAdd(&g_sumsq[cg0 + tid], s_sq[tid]);
    }
}

// Pass 2: fold stats + gamma/beta into per-channel scale/bias.
__global__ void finalize_kernel(const float* __restrict__ gamma,
                                const float* __restrict__ beta)
{
    int c = threadIdx.x;
    if (c >= Cc) return;
    const float inv = 1.0f / ((float)Nn * (float)Tt);
    float mean = g_sum[c] * inv;
    float var  = g_sumsq[c] * inv - mean * mean;
    float rstd = rsqrtf(var + 1e-5f);
    float sc   = gamma[c] * rstd;
    g_scale[c] = sc;
    g_bias[c]  = beta[c] - mean * sc;
}

// Pass 3: in-place normalize + relu. One block per (n,c) row, float4.
__global__ __launch_bounds__(256) void norm_kernel(float* __restrict__ out)
{
    const int row = blockIdx.x;          // n*C + c
    const int c   = row & (Cc - 1);
    const float sc = g_scale[c];
    const float b  = g_bias[c];
    float4* p = reinterpret_cast<float4*>(out + (size_t)row * Tt);
    const int tid = threadIdx.x;
    #pragma unroll
    for (int k = 0; k < (Tt / 4) / 256; k++) {
        float4 v = p[tid + k * 256];
        v.x = fmaxf(fmaf(v.x, sc, b), 0.0f);
        v.y = fmaxf(fmaf(v.y, sc, b), 0.0f);
        v.z = fmaxf(fmaf(v.z, sc, b), 0.0f);
        v.w = fmaxf(fmaf(v.w, sc, b), 0.0f);
        p[tid + k * 256] = v;
    }
}

extern "C" void kernel_launch(void* const* d_in, const int* in_sizes, int n_in,
                              void* d_out, int out_size)
{
    const float* x     = (const float*)d_in[0];
    const float* w     = (const float*)d_in[1];
    const float* gamma = (const float*)d_in[2];
    const float* beta  = (const float*)d_in[3];
    float* out = (float*)d_out;

    zero_kernel<<<1, 128>>>();
    conv_stats_kernel<<<dim3(Tt / TB, Cc / CG, Nn), 256>>>(x, w, out);
    finalize_kernel<<<1, 128>>>(gamma, beta);
    norm_kernel<<<Nn * Cc, 256>>>(out);
}

// round 4
// speedup vs baseline: 1.4289x; 1.4289x over previous
#include <cuda_runtime.h>

// S2Conv fused persistent kernel.
// N=64, C=128, T=2048, S=9. Block = 32 output channels x (4 slabs of 1 n x 1024 t).
// Phase 1: conv -> out, stats in regs. Grid barrier. Phase 2: normalize out in-place.

#define Nn 64
#define Cc 128
#define Tt 2048
#define Ss 9
#define CG 32          // output channels per block
#define ROWS 40        // CG + 8 halo
#define TBt 1024       // time tile
#define NBLK 128
#define NTHR 512

__device__ float g_sum[Cc];
__device__ float g_sumsq[Cc];
__device__ unsigned g_arrive;

__global__ void init_kernel() {
    int i = threadIdx.x;
    if (i < Cc) { g_sum[i] = 0.0f; g_sumsq[i] = 0.0f; }
    if (i == 0) g_arrive = 0u;
}

extern __shared__ float tile_mem[];   // ROWS x TBt floats = 160 KB

__global__ __launch_bounds__(NTHR, 1) void fused_kernel(
    const float* __restrict__ x,
    const float* __restrict__ w,
    const float* __restrict__ gamma,
    const float* __restrict__ beta,
    float* __restrict__ out)
{
    float (*tile)[TBt] = (float (*)[TBt])tile_mem;
    __shared__ float s_w[CG][12];          // padded
    __shared__ float s_scale[CG], s_bias[CG];

    const int bid  = blockIdx.x;
    const int grp  = bid >> 5;             // 0..3 channel group
    const int sb   = bid & 31;             // 0..31 slab block
    const int cg0  = grp * CG;
    const int tid  = threadIdx.x;
    const int wid  = tid >> 5;
    const int lane = tid & 31;
    const int g    = wid & 7;              // channel quad within group
    const int q    = wid >> 3;             // t half (0/1)
    const int lcb  = g * 4;

    if (tid < CG * Ss) {
        int cl = tid / Ss, s = tid % Ss;
        s_w[cl][s] = w[(cg0 + cl) * Ss + s];
    }

    float lsum[4] = {0.f, 0.f, 0.f, 0.f};
    float lsq[4]  = {0.f, 0.f, 0.f, 0.f};

    for (int sl = 0; sl < 4; sl++) {
        const int slab = sb * 4 + sl;      // 0..127
        const int n    = slab >> 1;
        const int t0   = (slab & 1) * TBt;

        __syncthreads();                   // tile reuse guard (also covers s_w on sl=0)

        // ---- Loader: tile[r][j] = xs[n, cg0-4+r, t0+j], pre-shifted, zero-padded.
        const float* xn = x + (size_t)n * Cc * Tt;
        for (int r = wid; r < ROWS; r += 16) {
            const int cc = cg0 - 4 + r;
            const bool rowok = (cc >= 0) && (cc < Cc);
            const int off = rowok ? (4 - (cc % 9)) : 0;
            const float* xr = xn + (size_t)(rowok ? cc : 0) * Tt;
            #pragma unroll
            for (int u = 0; u < TBt / 128; u++) {
                const int j  = u * 128 + lane * 4;
                const int ts = t0 + j + off;
                float4 v = make_float4(0.f, 0.f, 0.f, 0.f);
                if (rowok) {
                    if ((unsigned)(ts + 0) < (unsigned)Tt) v.x = xr[ts + 0];
                    if ((unsigned)(ts + 1) < (unsigned)Tt) v.y = xr[ts + 1];
                    if ((unsigned)(ts + 2) < (unsigned)Tt) v.z = xr[ts + 2];
                    if ((unsigned)(ts + 3) < (unsigned)Tt) v.w = xr[ts + 3];
                }
                *reinterpret_cast<float4*>(&tile[r][j]) = v;
            }
        }
        __syncthreads();

        // ---- Compute: warp (g,q) -> 4 channels x 512 t, lane -> 4 t per iter.
        float* outb = out + ((size_t)n * Cc + cg0 + lcb) * Tt + t0;
        #pragma unroll
        for (int it = 0; it < 4; it++) {
            const int j = q * 512 + it * 128 + lane * 4;
            float4 tp[12];
            #pragma unroll
            for (int r = 0; r < 12; r++)
                tp[r] = *reinterpret_cast<const float4*>(&tile[lcb + r][j]);
            #pragma unroll
            for (int cl = 0; cl < 4; cl++) {
                float4 a = make_float4(0.f, 0.f, 0.f, 0.f);
                #pragma unroll
                for (int s = 0; s < Ss; s++) {
                    const float wv = s_w[lcb + cl][s];
                    a.x = fmaf(wv, tp[cl + s].x, a.x);
                    a.y = fmaf(wv, tp[cl + s].y, a.y);
                    a.z = fmaf(wv, tp[cl + s].z, a.z);
                    a.w = fmaf(wv, tp[cl + s].w, a.w);
                }
                *reinterpret_cast<float4*>(outb + (size_t)cl * Tt + j) = a;
                lsum[cl] += (a.x + a.y) + (a.z + a.w);
                lsq[cl]   = fmaf(a.x, a.x, fmaf(a.y, a.y,
                            fmaf(a.z, a.z, fmaf(a.w, a.w, lsq[cl]))));
            }
        }
    }

    // ---- One reduction for the whole kernel.
    #pragma unroll
    for (int cl = 0; cl < 4; cl++) {
        #pragma unroll
        for (int o = 16; o > 0; o >>= 1) {
            lsum[cl] += __shfl_down_sync(0xffffffffu, lsum[cl], o);
            lsq[cl]  += __shfl_down_sync(0xffffffffu, lsq[cl],  o);
        }
    }
    if (lane == 0) {
        #pragma unroll
        for (int cl = 0; cl < 4; cl++) {
            atomicAdd(&g_sum[cg0 + lcb + cl],   lsum[cl]);
            atomicAdd(&g_sumsq[cg0 + lcb + cl], lsq[cl]);
        }
    }
    __syncthreads();

    // ---- Grid barrier (all 128 blocks resident: 1 CTA/SM by smem, 128 <= 148 SMs).
    if (tid == 0) {
        __threadfence();
        atomicAdd(&g_arrive, 1u);
        while (*(volatile unsigned*)&g_arrive < NBLK) { }
    }
    __syncthreads();
    __threadfence();

    // ---- Finalize per-channel scale/bias.
    if (tid < CG) {
        const int c = cg0 + tid;
        const float s1 = __ldcg(&g_sum[c]);
        const float s2 = __ldcg(&g_sumsq[c]);
        const float inv = 1.0f / ((float)Nn * (float)Tt);
        const float mean = s1 * inv;
        const float var  = s2 * inv - mean * mean;
        const float rstd = rsqrtf(var + 1e-5f);
        const float sc   = gamma[c] * rstd;
        s_scale[tid] = sc;
        s_bias[tid]  = beta[c] - mean * sc;
    }
    __syncthreads();

    // ---- Phase 2: normalize + relu the region this block wrote (L2-hot).
    for (int sl = 0; sl < 4; sl++) {
        const int slab = sb * 4 + sl;
        const int n    = slab >> 1;
        const int t0   = (slab & 1) * TBt;
        float* ob = out + ((size_t)n * Cc + cg0) * Tt + t0;
        #pragma unroll
        for (int k = 0; k < (CG * TBt / 4) / NTHR; k++) {
            const int idx = tid + k * NTHR;
            const int row = idx >> 8;            // 256 float4 per row
            const int col = (idx & 255) * 4;
            float4 v = *reinterpret_cast<float4*>(ob + (size_t)row * Tt + col);
            const float sc = s_scale[row];
            const float b  = s_bias[row];
            v.x = fmaxf(fmaf(v.x, sc, b), 0.0f);
            v.y = fmaxf(fmaf(v.y, sc, b), 0.0f);
            v.z = fmaxf(fmaf(v.z, sc, b), 0.0f);
            v.w = fmaxf(fmaf(v.w, sc, b), 0.0f);
            *reinterpret_cast<float4*>(ob + (size_t)row * Tt + col) = v;
        }
    }
}

extern "C" void kernel_launch(void* const* d_in, const int* in_sizes, int n_in,
                              void* d_out, int out_size)
{
    const float* x     = (const float*)d_in[0];
    const float* w     = (const float*)d_in[1];
    const float* gamma = (const float*)d_in[2];
    const float* beta  = (const float*)d_in[3];
    float* out = (float*)d_out;

    const int smem = ROWS * TBt * sizeof(float);   // 160 KB dynamic
    static bool attr_set = false;
    if (!attr_set) {
        cudaFuncSetAttribute(fused_kernel,
                             cudaFuncAttributeMaxDynamicSharedMemorySize, smem);
        attr_set = true;
    }

    init_kernel<<<1, 128>>>();
    fused_kernel<<<NBLK, NTHR, smem>>>(x, w, gamma, beta, out);
}